// round 14
// baseline (speedup 1.0000x reference)
#include <cuda_runtime.h>
#include <cuda_bf16.h>
#include <cstdint>

#define NROWS 2048
#define DFEAT 128
#define NT    32
#define TILE  64
#define NTJ   (NROWS / TILE)            // 32 tile rows
#define NBLK  (NTJ * (NTJ + 1) / 2)     // 528 upper-triangular tiles
#define PS    34                        // P tile row stride (floats)
#define NTHR  256
#define CNS   65                        // cn tile stride (floats)

// smem layout (bytes): 4 bf16 tiles [64][128] SW128 blocked-atom (16KB each)
#define XTB    16384
#define OFF_AH 0
#define OFF_AL 16384
#define OFF_BH 32768
#define OFF_BL 49152
#define OFF_PJ 65536                    // [64][PS] f32 = 8704B
#define OFF_PK 74240
#define OFF_RN 82944                    // rn[128]
#define SMEM_BYTES 83456                // -> 2 blocks/SM (166912 < 228KB)
// cn (64*65*4 = 16640B) overlays AH + head of AL after MMA

__device__ double g_acc;
__device__ int    g_count;
__device__ float  g_rn[NROWS];
__device__ uint4  g_hi[NROWS * 16];     // bf16 hi rows, 256B/row
__device__ uint4  g_lo[NROWS * 16];     // bf16 lo rows

// ---------------- packed f32x2 helpers ----------------
typedef unsigned long long u64t;
__device__ __forceinline__ u64t pack2(float lo, float hi) {
    u64t u; asm("mov.b64 %0, {%1, %2};" : "=l"(u) : "f"(lo), "f"(hi)); return u;
}
__device__ __forceinline__ void unpack2(u64t u, float& lo, float& hi) {
    asm("mov.b64 {%0, %1}, %2;" : "=f"(lo), "=f"(hi) : "l"(u));
}
__device__ __forceinline__ u64t add2(u64t a, u64t b) {
    u64t d; asm("add.rn.f32x2 %0, %1, %2;" : "=l"(d) : "l"(a), "l"(b)); return d;
}
__device__ __forceinline__ u64t lds2(const float* p) {
    float2 v = *reinterpret_cast<const float2*>(p);
    return pack2(v.x, v.y);
}

// ---------------- warp-MMA helpers (sm_80+ PTX) ----------------
__device__ __forceinline__ uint32_t smem_u32(const void* p) {
    uint32_t a;
    asm("{ .reg .u64 t; cvta.to.shared.u64 t, %1; cvt.u32.u64 %0, t; }" : "=r"(a) : "l"(p));
    return a;
}
__device__ __forceinline__ void ldsm4(uint32_t addr, uint32_t& r0, uint32_t& r1,
                                      uint32_t& r2, uint32_t& r3) {
    asm volatile("ldmatrix.sync.aligned.m8n8.x4.shared.b16 {%0,%1,%2,%3}, [%4];"
                 : "=r"(r0), "=r"(r1), "=r"(r2), "=r"(r3) : "r"(addr));
}
__device__ __forceinline__ void mma16816(float* d, const uint32_t* a,
                                         uint32_t b0, uint32_t b1) {
    asm volatile(
        "mma.sync.aligned.m16n8k16.row.col.f32.bf16.bf16.f32 "
        "{%0,%1,%2,%3}, {%4,%5,%6,%7}, {%8,%9}, {%0,%1,%2,%3};"
        : "+f"(d[0]), "+f"(d[1]), "+f"(d[2]), "+f"(d[3])
        : "r"(a[0]), "r"(a[1]), "r"(a[2]), "r"(a[3]), "r"(b0), "r"(b1));
}
__device__ __forceinline__ unsigned pack_bf16x2(float lo, float hi) {
    unsigned r; asm("cvt.rn.bf16x2.f32 %0, %1, %2;" : "=r"(r) : "f"(hi), "f"(lo)); return r;
}

// SW128 blocked-atom byte offset for a [64 rows][128 cols] bf16 tile
// atom = 8 rows x 64 cols (1024B); 8 atom-rows per 64-col block.
__device__ __forceinline__ uint32_t bf16_off(int row, int col) {
    uint32_t b = (uint32_t)(((row >> 3) + ((col >> 6) << 3)) * 1024
                            + (row & 7) * 128 + (col & 63) * 2);
    return b ^ (uint32_t)((row & 7) << 4);
}

// ---------------------------------------------------------------------------
// Prep kernel: per-row bf16 hi/lo split + inverse norms + accumulator reset.
// One warp per row; 256 blocks x 256 threads.
// ---------------------------------------------------------------------------
__global__ void prep_kernel(const float* __restrict__ X) {
    if (blockIdx.x == 0 && threadIdx.x == 0) { g_acc = 0.0; g_count = 0; }
    int w    = (blockIdx.x * blockDim.x + threadIdx.x) >> 5;
    int lane = threadIdx.x & 31;
    if (w >= NROWS) return;
    float4 v = ((const float4*)(X + (size_t)w * DFEAT))[lane];
    float s = v.x * v.x + v.y * v.y + v.z * v.z + v.w * v.w;
    #pragma unroll
    for (int o = 16; o > 0; o >>= 1) s += __shfl_xor_sync(0xffffffffu, s, o);
    if (lane == 0) g_rn[w] = rsqrtf(s);

    unsigned hw0 = pack_bf16x2(v.x, v.y);
    unsigned hw1 = pack_bf16x2(v.z, v.w);
    float r0 = v.x - __uint_as_float(hw0 << 16);
    float r1 = v.y - __uint_as_float(hw0 & 0xffff0000u);
    float r2 = v.z - __uint_as_float(hw1 << 16);
    float r3 = v.w - __uint_as_float(hw1 & 0xffff0000u);
    unsigned lw0 = pack_bf16x2(r0, r1);
    unsigned lw1 = pack_bf16x2(r2, r3);
    ((uint2*)g_hi)[w * 32 + lane] = make_uint2(hw0, hw1);
    ((uint2*)g_lo)[w * 32 + lane] = make_uint2(lw0, lw1);
}

// ---------------------------------------------------------------------------
// Pair kernel: 64x64 tiles, 256 threads, 2 blocks/SM.
// ---------------------------------------------------------------------------
__global__ void __launch_bounds__(NTHR, 2)
pair_kernel(const float* __restrict__ P,
            const float* __restrict__ scale_p,
            const float* __restrict__ target,
            float* __restrict__ out) {
    // ---- triangular decode: blockIdx.x -> (tj, tk), tk >= tj ----
    int idx = blockIdx.x;
    int tj = 0;
    while (idx >= NTJ - tj) { idx -= NTJ - tj; tj++; }
    const int tk = tj + idx;
    const int j0 = tj * TILE;
    const int k0 = tk * TILE;

    extern __shared__ char sm[];
    float* sPj = (float*)(sm + OFF_PJ);
    float* sPk = (float*)(sm + OFF_PK);   // negated
    float* rn  = (float*)(sm + OFF_RN);   // [0..63]=j rows, [64..127]=k rows
    float* cn  = (float*)(sm + 0);        // overlays AH/AL post-MMA
    const uint32_t sbase = smem_u32(sm);

    __shared__ float s_red[8];
    __shared__ int   s_last;

    const int tid  = threadIdx.x;
    const int wid  = tid >> 5;
    const int lane = tid & 31;
    const float scale = *scale_p;

    // ---- copy X tiles from precomputed global bf16 (16B chunks, swizzled) ----
    for (int i = tid; i < 4096; i += NTHR) {
        int t    = i >> 10;               // 0=AH 1=AL 2=BH 3=BL
        int rem  = i & 1023;
        int row  = rem >> 4;
        int c16  = rem & 15;              // 16B chunk -> col = c16*8
        int g0   = (t >= 2) ? k0 : j0;
        const uint4* src = (t & 1) ? g_lo : g_hi;
        uint4 val = src[(g0 + row) * 16 + c16];
        *(uint4*)(sm + t * XTB + bf16_off(row, c16 * 8)) = val;
    }
    // ---- P tiles (k negated) ----
    for (int i = tid; i < TILE * NT / 4; i += NTHR) {
        int row = i >> 3;
        int c4  = (i & 7) * 4;
        float4 vj = *(const float4*)(P + (size_t)(j0 + row) * NT + c4);
        float4 vk = *(const float4*)(P + (size_t)(k0 + row) * NT + c4);
        *(float2*)(sPj + row * PS + c4)     = make_float2(vj.x, vj.y);
        *(float2*)(sPj + row * PS + c4 + 2) = make_float2(vj.z, vj.w);
        *(float2*)(sPk + row * PS + c4)     = make_float2(-vk.x, -vk.y);
        *(float2*)(sPk + row * PS + c4 + 2) = make_float2(-vk.z, -vk.w);
    }
    if (tid < 128)
        rn[tid] = g_rn[(tid < 64) ? (j0 + tid) : (k0 + tid - 64)];
    __syncthreads();

    // ---- warp MMA: 8 warps, each a 32x16 Gram sub-tile; 3 bf16 split passes ----
    const int m0 = (wid & 1) * 32;
    const int n0 = (wid >> 1) * 16;
    float acc[2][2][4];
    #pragma unroll
    for (int mt = 0; mt < 2; mt++)
        #pragma unroll
        for (int nt = 0; nt < 2; nt++)
            #pragma unroll
            for (int q = 0; q < 4; q++) acc[mt][nt][q] = 0.0f;

    const int aRow  = m0 + (lane & 15);
    const int aCol0 = (lane >> 4) * 8;
    const int bRow  = n0 + (lane & 7) + (lane >> 4) * 8;
    const int bCol0 = ((lane >> 3) & 1) * 8;
    // row-dependent parts of bf16_off (col varies per kk)
    uint32_t aRP[2], aXor[2];
    #pragma unroll
    for (int mt = 0; mt < 2; mt++) {
        int r = aRow + mt * 16;
        aRP[mt]  = (uint32_t)((r >> 3) * 1024 + (r & 7) * 128);
        aXor[mt] = (uint32_t)((r & 7) << 4);
    }
    const uint32_t bRP  = (uint32_t)((bRow >> 3) * 1024 + (bRow & 7) * 128);
    const uint32_t bXor = (uint32_t)((bRow & 7) << 4);

    #pragma unroll
    for (int pass = 0; pass < 3; pass++) {
        const uint32_t aBase = sbase + (pass == 2 ? OFF_AL : OFF_AH);
        const uint32_t bBase = sbase + (pass == 1 ? OFF_BL : OFF_BH);
        #pragma unroll
        for (int kk = 0; kk < 8; kk++) {
            uint32_t a[2][4];
            #pragma unroll
            for (int mt = 0; mt < 2; mt++) {
                int col = aCol0 + kk * 16;
                uint32_t ad = aBase + aRP[mt] + (uint32_t)((col >> 6) << 13)
                            + (((uint32_t)((col & 63) * 2)) ^ aXor[mt]);
                ldsm4(ad, a[mt][0], a[mt][1], a[mt][2], a[mt][3]);
            }
            uint32_t b[4];
            {
                int col = bCol0 + kk * 16;
                uint32_t bd = bBase + bRP + (uint32_t)((col >> 6) << 13)
                            + (((uint32_t)((col & 63) * 2)) ^ bXor);
                ldsm4(bd, b[0], b[1], b[2], b[3]);
            }
            #pragma unroll
            for (int mt = 0; mt < 2; mt++) {
                mma16816(acc[mt][0], a[mt], b[0], b[1]);
                mma16816(acc[mt][1], a[mt], b[2], b[3]);
            }
        }
    }
    __syncthreads();   // all ldsm reads done -> AH/AL reusable as cn

    // ---- fold norms + scale, stage cn[m][n] to smem ----
    {
        const int g = lane >> 2;
        const int q = lane & 3;
        #pragma unroll
        for (int mt = 0; mt < 2; mt++)
            #pragma unroll
            for (int nt = 0; nt < 2; nt++)
                #pragma unroll
                for (int r = 0; r < 4; r++) {
                    int m = m0 + mt * 16 + 8 * (r >> 1) + g;
                    int n = n0 + nt * 8 + q * 2 + (r & 1);
                    float cosv = acc[mt][nt][r] * rn[m] * rn[64 + n];
                    float v = scale * cosv - scale;       // -scale*(1-cos)
                    cn[m * CNS + n] = ((k0 + n) > (j0 + m)) ? v : -1.0e30f;
                }
    }
    __syncthreads();

    // ---- hinge: 4x4 register tile, packed f32x2 ----
    const int tx = tid & 15;      // kl = tx + 16*s
    const int ty = tid >> 4;      // jl = ty + 16*r

    float cnr[4][4];
    #pragma unroll
    for (int r = 0; r < 4; r++)
        #pragma unroll
        for (int s = 0; s < 4; s++)
            cnr[r][s] = cn[(ty + 16 * r) * CNS + tx + 16 * s];

    u64t hs2[4];
    #pragma unroll
    for (int s = 0; s < 4; s++) hs2[s] = 0ULL;

    const float* pjb = sPj + ty * PS;
    const float* pkb = sPk + tx * PS;
    #pragma unroll 4
    for (int t2 = 0; t2 < NT / 2; t2++) {
        u64t pj[4], nk[4];
        #pragma unroll
        for (int r = 0; r < 4; r++) pj[r] = lds2(pjb + (16 * r) * PS + 2 * t2);
        #pragma unroll
        for (int s = 0; s < 4; s++) nk[s] = lds2(pkb + (16 * s) * PS + 2 * t2);
        #pragma unroll
        for (int r = 0; r < 4; r++)
            #pragma unroll
            for (int s = 0; s < 4; s++) {
                u64t d2v = add2(pj[r], nk[s]);
                float lo, hi; unpack2(d2v, lo, hi);
                float tl = fabsf(lo) + cnr[r][s];
                float th = fabsf(hi) + cnr[r][s];
                tl = fmaxf(tl, 0.0f);
                th = fmaxf(th, 0.0f);
                hs2[s] = add2(hs2[s], pack2(tl, th));
            }
    }

    float hsum = 0.0f;
    #pragma unroll
    for (int s = 0; s < 4; s++) {
        float lo, hi; unpack2(hs2[s], lo, hi);
        hsum += lo + hi;
    }

    // ---- reduce + accumulate + epilogue ----
    #pragma unroll
    for (int o = 16; o > 0; o >>= 1) hsum += __shfl_xor_sync(0xffffffffu, hsum, o);
    if (lane == 0) s_red[wid] = hsum;
    __syncthreads();
    if (tid == 0) {
        float bs = 0.0f;
        #pragma unroll
        for (int w = 0; w < NTHR / 32; w++) bs += s_red[w];
        atomicAdd(&g_acc, (double)bs);
        __threadfence();
        int t = atomicAdd(&g_count, 1);
        s_last = (t == NBLK - 1);
    }
    __syncthreads();
    if (s_last && tid == 0) {
        double R  = g_acc;
        double mf = 2.0 * R / ((double)NROWS * (double)(NROWS - 1) * (double)NT);
        out[0] = fmaxf((float)mf - *target, 0.0f);
    }
}

extern "C" void kernel_launch(void* const* d_in, const int* in_sizes, int n_in,
                              void* d_out, int out_size) {
    const float* target = (const float*)d_in[0];
    const float* pred   = (const float*)d_in[1];
    const float* X      = (const float*)d_in[2];
    const float* scale  = (const float*)d_in[4];
    float* out = (float*)d_out;

    cudaFuncSetAttribute(pair_kernel,
                         cudaFuncAttributeMaxDynamicSharedMemorySize, SMEM_BYTES);
    prep_kernel<<<NROWS / 8, 256>>>(X);
    pair_kernel<<<NBLK, NTHR, SMEM_BYTES>>>(pred, scale, target, out);
}

// round 16
// speedup vs baseline: 1.0757x; 1.0757x over previous
#include <cuda_runtime.h>
#include <cuda_bf16.h>
#include <cstdint>

#define NROWS 2048
#define DFEAT 128
#define NT    32
#define TILE  64
#define NTJ   (NROWS / TILE)            // 32 tile rows
#define NBLK  (NTJ * (NTJ + 1) / 2)     // 528 upper-triangular tiles
#define PS    34                        // P tile row stride (floats)
#define NTHR  256
#define CNS   65                        // cn tile stride (floats)

// smem layout (bytes): 3 bf16 tiles [64][128] SW128 blocked-atom (16KB each)
#define XTB    16384
#define OFF_AH 0
#define OFF_AL 16384
#define OFF_BH 32768
#define OFF_PJ 49152                    // [64][PS] f32 = 8704B
#define OFF_PK 57856
#define OFF_RN 66560                    // rn[128] = 512B
#define SMEM_BYTES 67072                // 3 blocks/SM (201216 < 228KB)
// cn (64*65*4 = 16640B) overlays AH + head of AL after MMA

__device__ double g_acc;
__device__ int    g_count;
__device__ float  g_rn[NROWS];
__device__ uint4  g_hi[NROWS * 16];     // bf16 hi rows, 256B/row
__device__ uint4  g_lo[NROWS * 16];     // bf16 lo rows

// ---------------- packed f32x2 helpers ----------------
typedef unsigned long long u64t;
__device__ __forceinline__ u64t pack2(float lo, float hi) {
    u64t u; asm("mov.b64 %0, {%1, %2};" : "=l"(u) : "f"(lo), "f"(hi)); return u;
}
__device__ __forceinline__ void unpack2(u64t u, float& lo, float& hi) {
    asm("mov.b64 {%0, %1}, %2;" : "=f"(lo), "=f"(hi) : "l"(u));
}
__device__ __forceinline__ u64t add2(u64t a, u64t b) {
    u64t d; asm("add.rn.f32x2 %0, %1, %2;" : "=l"(d) : "l"(a), "l"(b)); return d;
}
__device__ __forceinline__ u64t lds2(const float* p) {
    float2 v = *reinterpret_cast<const float2*>(p);
    return pack2(v.x, v.y);
}

// ---------------- warp-MMA helpers (sm_80+ PTX) ----------------
__device__ __forceinline__ uint32_t smem_u32(const void* p) {
    uint32_t a;
    asm("{ .reg .u64 t; cvta.to.shared.u64 t, %1; cvt.u32.u64 %0, t; }" : "=r"(a) : "l"(p));
    return a;
}
__device__ __forceinline__ void ldsm4(uint32_t addr, uint32_t& r0, uint32_t& r1,
                                      uint32_t& r2, uint32_t& r3) {
    asm volatile("ldmatrix.sync.aligned.m8n8.x4.shared.b16 {%0,%1,%2,%3}, [%4];"
                 : "=r"(r0), "=r"(r1), "=r"(r2), "=r"(r3) : "r"(addr));
}
__device__ __forceinline__ void mma16816(float* d, const uint32_t* a,
                                         uint32_t b0, uint32_t b1) {
    asm volatile(
        "mma.sync.aligned.m16n8k16.row.col.f32.bf16.bf16.f32 "
        "{%0,%1,%2,%3}, {%4,%5,%6,%7}, {%8,%9}, {%0,%1,%2,%3};"
        : "+f"(d[0]), "+f"(d[1]), "+f"(d[2]), "+f"(d[3])
        : "r"(a[0]), "r"(a[1]), "r"(a[2]), "r"(a[3]), "r"(b0), "r"(b1));
}
__device__ __forceinline__ unsigned pack_bf16x2(float lo, float hi) {
    unsigned r; asm("cvt.rn.bf16x2.f32 %0, %1, %2;" : "=r"(r) : "f"(hi), "f"(lo)); return r;
}

// SW128 blocked-atom byte offset for a [64 rows][128 cols] bf16 tile
__device__ __forceinline__ uint32_t bf16_off(int row, int col) {
    uint32_t b = (uint32_t)(((row >> 3) + ((col >> 6) << 3)) * 1024
                            + (row & 7) * 128 + (col & 63) * 2);
    return b ^ (uint32_t)((row & 7) << 4);
}

// ---------------------------------------------------------------------------
// Prep kernel: per-row bf16 hi/lo split + inverse norms + accumulator reset.
// ---------------------------------------------------------------------------
__global__ void prep_kernel(const float* __restrict__ X) {
    if (blockIdx.x == 0 && threadIdx.x == 0) { g_acc = 0.0; g_count = 0; }
    int w    = (blockIdx.x * blockDim.x + threadIdx.x) >> 5;
    int lane = threadIdx.x & 31;
    if (w >= NROWS) return;
    float4 v = ((const float4*)(X + (size_t)w * DFEAT))[lane];
    float s = v.x * v.x + v.y * v.y + v.z * v.z + v.w * v.w;
    #pragma unroll
    for (int o = 16; o > 0; o >>= 1) s += __shfl_xor_sync(0xffffffffu, s, o);
    if (lane == 0) g_rn[w] = rsqrtf(s);

    unsigned hw0 = pack_bf16x2(v.x, v.y);
    unsigned hw1 = pack_bf16x2(v.z, v.w);
    float r0 = v.x - __uint_as_float(hw0 << 16);
    float r1 = v.y - __uint_as_float(hw0 & 0xffff0000u);
    float r2 = v.z - __uint_as_float(hw1 << 16);
    float r3 = v.w - __uint_as_float(hw1 & 0xffff0000u);
    unsigned lw0 = pack_bf16x2(r0, r1);
    unsigned lw1 = pack_bf16x2(r2, r3);
    ((uint2*)g_hi)[w * 32 + lane] = make_uint2(hw0, hw1);
    ((uint2*)g_lo)[w * 32 + lane] = make_uint2(lw0, lw1);
}

// ---------------------------------------------------------------------------
// Pair kernel: 64x64 tiles, 256 threads, 3 blocks/SM.
// ---------------------------------------------------------------------------
__global__ void __launch_bounds__(NTHR, 3)
pair_kernel(const float* __restrict__ P,
            const float* __restrict__ scale_p,
            const float* __restrict__ target,
            float* __restrict__ out) {
    // ---- triangular decode: blockIdx.x -> (tj, tk), tk >= tj ----
    int idx = blockIdx.x;
    int tj = 0;
    while (idx >= NTJ - tj) { idx -= NTJ - tj; tj++; }
    const int tk = tj + idx;
    const int j0 = tj * TILE;
    const int k0 = tk * TILE;

    extern __shared__ char sm[];
    float* sPj = (float*)(sm + OFF_PJ);
    float* sPk = (float*)(sm + OFF_PK);   // negated
    float* rn  = (float*)(sm + OFF_RN);   // [0..63]=j rows, [64..127]=k rows
    float* cn  = (float*)(sm + 0);        // overlays AH/AL post-MMA
    const uint32_t sbase = smem_u32(sm);

    __shared__ float s_red[8];
    __shared__ int   s_last;

    const int tid  = threadIdx.x;
    const int wid  = tid >> 5;
    const int lane = tid & 31;
    const float scale = *scale_p;

    // ---- copy X tiles: AH, AL from j rows; BH from k rows (16B swizzled) ----
    for (int i = tid; i < 3072; i += NTHR) {
        int t    = i >> 10;               // 0=AH 1=AL 2=BH
        int rem  = i & 1023;
        int row  = rem >> 4;
        int c16  = rem & 15;              // 16B chunk -> col = c16*8
        int g0   = (t == 2) ? k0 : j0;
        const uint4* src = (t == 1) ? g_lo : g_hi;
        uint4 val = src[(g0 + row) * 16 + c16];
        *(uint4*)(sm + t * XTB + bf16_off(row, c16 * 8)) = val;
    }
    // ---- P tiles (k negated) ----
    for (int i = tid; i < TILE * NT / 4; i += NTHR) {
        int row = i >> 3;
        int c4  = (i & 7) * 4;
        float4 vj = *(const float4*)(P + (size_t)(j0 + row) * NT + c4);
        float4 vk = *(const float4*)(P + (size_t)(k0 + row) * NT + c4);
        *(float2*)(sPj + row * PS + c4)     = make_float2(vj.x, vj.y);
        *(float2*)(sPj + row * PS + c4 + 2) = make_float2(vj.z, vj.w);
        *(float2*)(sPk + row * PS + c4)     = make_float2(-vk.x, -vk.y);
        *(float2*)(sPk + row * PS + c4 + 2) = make_float2(-vk.z, -vk.w);
    }
    if (tid < 128)
        rn[tid] = g_rn[(tid < 64) ? (j0 + tid) : (k0 + tid - 64)];
    __syncthreads();

    // ---- warp MMA: 8 warps, each 32x16 Gram sub-tile; 2 passes (AHxBH, ALxBH) ----
    const int m0 = (wid & 1) * 32;
    const int n0 = (wid >> 1) * 16;
    float acc[2][2][4];
    #pragma unroll
    for (int mt = 0; mt < 2; mt++)
        #pragma unroll
        for (int nt = 0; nt < 2; nt++)
            #pragma unroll
            for (int q = 0; q < 4; q++) acc[mt][nt][q] = 0.0f;

    const int aRow  = m0 + (lane & 15);
    const int aCol0 = (lane >> 4) * 8;
    const int bRow  = n0 + (lane & 7) + (lane >> 4) * 8;
    const int bCol0 = ((lane >> 3) & 1) * 8;
    uint32_t aRP[2], aXor[2];
    #pragma unroll
    for (int mt = 0; mt < 2; mt++) {
        int r = aRow + mt * 16;
        aRP[mt]  = (uint32_t)((r >> 3) * 1024 + (r & 7) * 128);
        aXor[mt] = (uint32_t)((r & 7) << 4);
    }
    const uint32_t bRP  = (uint32_t)((bRow >> 3) * 1024 + (bRow & 7) * 128);
    const uint32_t bXor = (uint32_t)((bRow & 7) << 4);

    #pragma unroll
    for (int pass = 0; pass < 2; pass++) {
        const uint32_t aBase = sbase + (pass ? OFF_AL : OFF_AH);
        const uint32_t bBase = sbase + OFF_BH;
        #pragma unroll
        for (int kk = 0; kk < 8; kk++) {
            uint32_t a[2][4];
            #pragma unroll
            for (int mt = 0; mt < 2; mt++) {
                int col = aCol0 + kk * 16;
                uint32_t ad = aBase + aRP[mt] + (uint32_t)((col >> 6) << 13)
                            + (((uint32_t)((col & 63) * 2)) ^ aXor[mt]);
                ldsm4(ad, a[mt][0], a[mt][1], a[mt][2], a[mt][3]);
            }
            uint32_t b[4];
            {
                int col = bCol0 + kk * 16;
                uint32_t bd = bBase + bRP + (uint32_t)((col >> 6) << 13)
                            + (((uint32_t)((col & 63) * 2)) ^ bXor);
                ldsm4(bd, b[0], b[1], b[2], b[3]);
            }
            #pragma unroll
            for (int mt = 0; mt < 2; mt++) {
                mma16816(acc[mt][0], a[mt], b[0], b[1]);
                mma16816(acc[mt][1], a[mt], b[2], b[3]);
            }
        }
    }
    __syncthreads();   // all ldsm reads done -> AH/AL reusable as cn

    // ---- fold norms + scale, stage cn[m][n] to smem ----
    {
        const int g = lane >> 2;
        const int q = lane & 3;
        #pragma unroll
        for (int mt = 0; mt < 2; mt++)
            #pragma unroll
            for (int nt = 0; nt < 2; nt++)
                #pragma unroll
                for (int r = 0; r < 4; r++) {
                    int m = m0 + mt * 16 + 8 * (r >> 1) + g;
                    int n = n0 + nt * 8 + q * 2 + (r & 1);
                    float cosv = acc[mt][nt][r] * rn[m] * rn[64 + n];
                    float v = scale * cosv - scale;       // -scale*(1-cos)
                    cn[m * CNS + n] = ((k0 + n) > (j0 + m)) ? v : -1.0e30f;
                }
    }
    __syncthreads();

    // ---- hinge: 4x4 register tile, f32x2 diff + scalar accumulate ----
    const int tx = tid & 15;      // kl = tx + 16*s
    const int ty = tid >> 4;      // jl = ty + 16*r

    float cnr[4][4];
    #pragma unroll
    for (int r = 0; r < 4; r++)
        #pragma unroll
        for (int s = 0; s < 4; s++)
            cnr[r][s] = cn[(ty + 16 * r) * CNS + tx + 16 * s];

    float hsl[4], hsh[4];
    #pragma unroll
    for (int s = 0; s < 4; s++) { hsl[s] = 0.0f; hsh[s] = 0.0f; }

    const float* pjb = sPj + ty * PS;
    const float* pkb = sPk + tx * PS;
    #pragma unroll 4
    for (int t2 = 0; t2 < NT / 2; t2++) {
        u64t pj[4], nk[4];
        #pragma unroll
        for (int r = 0; r < 4; r++) pj[r] = lds2(pjb + (16 * r) * PS + 2 * t2);
        #pragma unroll
        for (int s = 0; s < 4; s++) nk[s] = lds2(pkb + (16 * s) * PS + 2 * t2);
        #pragma unroll
        for (int r = 0; r < 4; r++)
            #pragma unroll
            for (int s = 0; s < 4; s++) {
                u64t d2v = add2(pj[r], nk[s]);            // {pj-pk} x2 (FADD2)
                float lo, hi; unpack2(d2v, lo, hi);
                float tl = fabsf(lo) + cnr[r][s];         // FADD |src| modifier
                float th = fabsf(hi) + cnr[r][s];
                tl = fmaxf(tl, 0.0f);                     // FMNMX (alu pipe)
                th = fmaxf(th, 0.0f);
                hsl[s] += tl;                             // scalar FADD accumulate
                hsh[s] += th;
            }
    }

    float hsum = 0.0f;
    #pragma unroll
    for (int s = 0; s < 4; s++) hsum += hsl[s] + hsh[s];

    // ---- reduce + accumulate + epilogue ----
    #pragma unroll
    for (int o = 16; o > 0; o >>= 1) hsum += __shfl_xor_sync(0xffffffffu, hsum, o);
    if (lane == 0) s_red[wid] = hsum;
    __syncthreads();
    if (tid == 0) {
        float bs = 0.0f;
        #pragma unroll
        for (int w = 0; w < NTHR / 32; w++) bs += s_red[w];
        atomicAdd(&g_acc, (double)bs);
        __threadfence();
        int t = atomicAdd(&g_count, 1);
        s_last = (t == NBLK - 1);
    }
    __syncthreads();
    if (s_last && tid == 0) {
        double R  = g_acc;
        double mf = 2.0 * R / ((double)NROWS * (double)(NROWS - 1) * (double)NT);
        out[0] = fmaxf((float)mf - *target, 0.0f);
    }
}

extern "C" void kernel_launch(void* const* d_in, const int* in_sizes, int n_in,
                              void* d_out, int out_size) {
    const float* target = (const float*)d_in[0];
    const float* pred   = (const float*)d_in[1];
    const float* X      = (const float*)d_in[2];
    const float* scale  = (const float*)d_in[4];
    float* out = (float*)d_out;

    cudaFuncSetAttribute(pair_kernel,
                         cudaFuncAttributeMaxDynamicSharedMemorySize, SMEM_BYTES);
    prep_kernel<<<NROWS / 8, 256>>>(X);
    pair_kernel<<<NBLK, NTHR, SMEM_BYTES>>>(pred, scale, target, out);
}

// round 17
// speedup vs baseline: 1.1695x; 1.0871x over previous
#include <cuda_runtime.h>
#include <cuda_bf16.h>
#include <cstdint>

#define NROWS 2048
#define DFEAT 128
#define NT    32
#define TILE  64
#define NTJ   (NROWS / TILE)            // 32 tile rows
#define NBLK  (NTJ * (NTJ + 1) / 2)     // 528 upper-triangular tiles
#define PS    36                        // P tile row stride (floats, /4 for float4)
#define NTHR  256
#define CNS   65                        // cn tile stride (floats)

// smem layout (bytes): 3 bf16 tiles [64][128] SW128 blocked-atom (16KB each)
#define XTB    16384
#define OFF_AH 0
#define OFF_AL 16384
#define OFF_BH 32768
#define OFF_PJ 49152                    // [64][PS] f32 = 9216B
#define OFF_PK 58368
#define OFF_RN 67584                    // rn[128] = 512B
#define SMEM_BYTES 68096                // 3 blocks/SM (204288 < 228KB)
// cn (64*65*4 = 16640B) overlays AH + head of AL after MMA

__device__ double g_acc;
__device__ int    g_count;
__device__ float  g_rn[NROWS];
__device__ uint4  g_hi[NROWS * 16];     // bf16 hi rows, 256B/row
__device__ uint4  g_lo[NROWS * 16];     // bf16 lo rows

// ---------------- packed f32x2 helpers ----------------
typedef unsigned long long u64t;
__device__ __forceinline__ u64t pack2(float lo, float hi) {
    u64t u; asm("mov.b64 %0, {%1, %2};" : "=l"(u) : "f"(lo), "f"(hi)); return u;
}
__device__ __forceinline__ void unpack2(u64t u, float& lo, float& hi) {
    asm("mov.b64 {%0, %1}, %2;" : "=f"(lo), "=f"(hi) : "l"(u));
}
__device__ __forceinline__ u64t add2(u64t a, u64t b) {
    u64t d; asm("add.rn.f32x2 %0, %1, %2;" : "=l"(d) : "l"(a), "l"(b)); return d;
}

// ---------------- warp-MMA helpers (sm_80+ PTX) ----------------
__device__ __forceinline__ uint32_t smem_u32(const void* p) {
    uint32_t a;
    asm("{ .reg .u64 t; cvta.to.shared.u64 t, %1; cvt.u32.u64 %0, t; }" : "=r"(a) : "l"(p));
    return a;
}
__device__ __forceinline__ void ldsm4(uint32_t addr, uint32_t& r0, uint32_t& r1,
                                      uint32_t& r2, uint32_t& r3) {
    asm volatile("ldmatrix.sync.aligned.m8n8.x4.shared.b16 {%0,%1,%2,%3}, [%4];"
                 : "=r"(r0), "=r"(r1), "=r"(r2), "=r"(r3) : "r"(addr));
}
__device__ __forceinline__ void mma16816(float* d, const uint32_t* a,
                                         uint32_t b0, uint32_t b1) {
    asm volatile(
        "mma.sync.aligned.m16n8k16.row.col.f32.bf16.bf16.f32 "
        "{%0,%1,%2,%3}, {%4,%5,%6,%7}, {%8,%9}, {%0,%1,%2,%3};"
        : "+f"(d[0]), "+f"(d[1]), "+f"(d[2]), "+f"(d[3])
        : "r"(a[0]), "r"(a[1]), "r"(a[2]), "r"(a[3]), "r"(b0), "r"(b1));
}
__device__ __forceinline__ unsigned pack_bf16x2(float lo, float hi) {
    unsigned r; asm("cvt.rn.bf16x2.f32 %0, %1, %2;" : "=r"(r) : "f"(hi), "f"(lo)); return r;
}

// SW128 blocked-atom byte offset for a [64 rows][128 cols] bf16 tile
__device__ __forceinline__ uint32_t bf16_off(int row, int col) {
    uint32_t b = (uint32_t)(((row >> 3) + ((col >> 6) << 3)) * 1024
                            + (row & 7) * 128 + (col & 63) * 2);
    return b ^ (uint32_t)((row & 7) << 4);
}

// ---------------------------------------------------------------------------
// Prep kernel: per-row bf16 hi/lo split + inverse norms + accumulator reset.
// ---------------------------------------------------------------------------
__global__ void prep_kernel(const float* __restrict__ X) {
    if (blockIdx.x == 0 && threadIdx.x == 0) { g_acc = 0.0; g_count = 0; }
    int w    = (blockIdx.x * blockDim.x + threadIdx.x) >> 5;
    int lane = threadIdx.x & 31;
    if (w >= NROWS) return;
    float4 v = ((const float4*)(X + (size_t)w * DFEAT))[lane];
    float s = v.x * v.x + v.y * v.y + v.z * v.z + v.w * v.w;
    #pragma unroll
    for (int o = 16; o > 0; o >>= 1) s += __shfl_xor_sync(0xffffffffu, s, o);
    if (lane == 0) g_rn[w] = rsqrtf(s);

    unsigned hw0 = pack_bf16x2(v.x, v.y);
    unsigned hw1 = pack_bf16x2(v.z, v.w);
    float r0 = v.x - __uint_as_float(hw0 << 16);
    float r1 = v.y - __uint_as_float(hw0 & 0xffff0000u);
    float r2 = v.z - __uint_as_float(hw1 << 16);
    float r3 = v.w - __uint_as_float(hw1 & 0xffff0000u);
    unsigned lw0 = pack_bf16x2(r0, r1);
    unsigned lw1 = pack_bf16x2(r2, r3);
    ((uint2*)g_hi)[w * 32 + lane] = make_uint2(hw0, hw1);
    ((uint2*)g_lo)[w * 32 + lane] = make_uint2(lw0, lw1);
}

// ---------------------------------------------------------------------------
// Pair kernel: 64x64 tiles, 256 threads, 3 blocks/SM.
// ---------------------------------------------------------------------------
__global__ void __launch_bounds__(NTHR, 3)
pair_kernel(const float* __restrict__ P,
            const float* __restrict__ scale_p,
            const float* __restrict__ target,
            float* __restrict__ out) {
    // ---- triangular decode: blockIdx.x -> (tj, tk), tk >= tj ----
    int idx = blockIdx.x;
    int tj = 0;
    while (idx >= NTJ - tj) { idx -= NTJ - tj; tj++; }
    const int tk = tj + idx;
    const int j0 = tj * TILE;
    const int k0 = tk * TILE;

    extern __shared__ char sm[];
    float* sPj = (float*)(sm + OFF_PJ);
    float* sPk = (float*)(sm + OFF_PK);   // negated
    float* rn  = (float*)(sm + OFF_RN);   // [0..63]=j rows, [64..127]=k rows
    float* cn  = (float*)(sm + 0);        // overlays AH/AL post-MMA
    const uint32_t sbase = smem_u32(sm);

    __shared__ float s_red[8];
    __shared__ int   s_last;

    const int tid  = threadIdx.x;
    const int wid  = tid >> 5;
    const int lane = tid & 31;
    const float scale = *scale_p;

    // ---- copy X tiles: AH, AL from j rows; BH from k rows (16B swizzled) ----
    for (int i = tid; i < 3072; i += NTHR) {
        int t    = i >> 10;               // 0=AH 1=AL 2=BH
        int rem  = i & 1023;
        int row  = rem >> 4;
        int c16  = rem & 15;              // 16B chunk -> col = c16*8
        int g0   = (t == 2) ? k0 : j0;
        const uint4* src = (t == 1) ? g_lo : g_hi;
        uint4 val = src[(g0 + row) * 16 + c16];
        *(uint4*)(sm + t * XTB + bf16_off(row, c16 * 8)) = val;
    }
    // ---- P tiles (k negated) ----
    for (int i = tid; i < TILE * NT / 4; i += NTHR) {
        int row = i >> 3;
        int c4  = (i & 7) * 4;
        float4 vj = *(const float4*)(P + (size_t)(j0 + row) * NT + c4);
        float4 vk = *(const float4*)(P + (size_t)(k0 + row) * NT + c4);
        *(float4*)(sPj + row * PS + c4) = vj;
        *(float4*)(sPk + row * PS + c4) = make_float4(-vk.x, -vk.y, -vk.z, -vk.w);
    }
    if (tid < 128)
        rn[tid] = g_rn[(tid < 64) ? (j0 + tid) : (k0 + tid - 64)];
    __syncthreads();

    // ---- warp MMA: 8 warps, each 32x16 Gram sub-tile; 2 passes (AHxBH, ALxBH) ----
    const int m0 = (wid & 1) * 32;
    const int n0 = (wid >> 1) * 16;
    float acc[2][2][4];
    #pragma unroll
    for (int mt = 0; mt < 2; mt++)
        #pragma unroll
        for (int nt = 0; nt < 2; nt++)
            #pragma unroll
            for (int q = 0; q < 4; q++) acc[mt][nt][q] = 0.0f;

    const int aRow  = m0 + (lane & 15);
    const int aCol0 = (lane >> 4) * 8;
    const int bRow  = n0 + (lane & 7) + (lane >> 4) * 8;
    const int bCol0 = ((lane >> 3) & 1) * 8;
    uint32_t aRP[2], aXor[2];
    #pragma unroll
    for (int mt = 0; mt < 2; mt++) {
        int r = aRow + mt * 16;
        aRP[mt]  = (uint32_t)((r >> 3) * 1024 + (r & 7) * 128);
        aXor[mt] = (uint32_t)((r & 7) << 4);
    }
    const uint32_t bRP  = (uint32_t)((bRow >> 3) * 1024 + (bRow & 7) * 128);
    const uint32_t bXor = (uint32_t)((bRow & 7) << 4);

    #pragma unroll
    for (int pass = 0; pass < 2; pass++) {
        const uint32_t aBase = sbase + (pass ? OFF_AL : OFF_AH);
        const uint32_t bBase = sbase + OFF_BH;
        #pragma unroll
        for (int kk = 0; kk < 8; kk++) {
            uint32_t a[2][4];
            #pragma unroll
            for (int mt = 0; mt < 2; mt++) {
                int col = aCol0 + kk * 16;
                uint32_t ad = aBase + aRP[mt] + (uint32_t)((col >> 6) << 13)
                            + (((uint32_t)((col & 63) * 2)) ^ aXor[mt]);
                ldsm4(ad, a[mt][0], a[mt][1], a[mt][2], a[mt][3]);
            }
            uint32_t b[4];
            {
                int col = bCol0 + kk * 16;
                uint32_t bd = bBase + bRP + (uint32_t)((col >> 6) << 13)
                            + (((uint32_t)((col & 63) * 2)) ^ bXor);
                ldsm4(bd, b[0], b[1], b[2], b[3]);
            }
            #pragma unroll
            for (int mt = 0; mt < 2; mt++) {
                mma16816(acc[mt][0], a[mt], b[0], b[1]);
                mma16816(acc[mt][1], a[mt], b[2], b[3]);
            }
        }
    }
    __syncthreads();   // all ldsm reads done -> AH/AL reusable as cn

    // ---- fold norms + scale, stage cn[m][n] to smem ----
    {
        const int g = lane >> 2;
        const int q = lane & 3;
        #pragma unroll
        for (int mt = 0; mt < 2; mt++)
            #pragma unroll
            for (int nt = 0; nt < 2; nt++)
                #pragma unroll
                for (int r = 0; r < 4; r++) {
                    int m = m0 + mt * 16 + 8 * (r >> 1) + g;
                    int n = n0 + nt * 8 + q * 2 + (r & 1);
                    float cosv = acc[mt][nt][r] * rn[m] * rn[64 + n];
                    float v = scale * cosv - scale;       // -scale*(1-cos)
                    cn[m * CNS + n] = ((k0 + n) > (j0 + m)) ? v : -1.0e30f;
                }
    }
    __syncthreads();

    // ---- hinge: 4x4 register tile; FADD.SAT relu (|d|+cn < 1 always),
    //      packed f32x2 diff + packed accumulate, float4 P loads ----
    const int tx = tid & 15;      // kl = tx + 16*s
    const int ty = tid >> 4;      // jl = ty + 16*r

    float cnr[4][4];
    #pragma unroll
    for (int r = 0; r < 4; r++)
        #pragma unroll
        for (int s = 0; s < 4; s++)
            cnr[r][s] = cn[(ty + 16 * r) * CNS + tx + 16 * s];

    u64t hs2[4];
    #pragma unroll
    for (int s = 0; s < 4; s++) hs2[s] = 0ULL;

    const float* pjb = sPj + ty * PS;
    const float* pkb = sPk + tx * PS;
    #pragma unroll 2
    for (int t4 = 0; t4 < NT / 4; t4++) {
        u64t pj[4][2], nk[4][2];
        #pragma unroll
        for (int r = 0; r < 4; r++) {
            float4 v = *(const float4*)(pjb + (16 * r) * PS + 4 * t4);
            pj[r][0] = pack2(v.x, v.y);
            pj[r][1] = pack2(v.z, v.w);
        }
        #pragma unroll
        for (int s = 0; s < 4; s++) {
            float4 v = *(const float4*)(pkb + (16 * s) * PS + 4 * t4);
            nk[s][0] = pack2(v.x, v.y);
            nk[s][1] = pack2(v.z, v.w);
        }
        #pragma unroll
        for (int r = 0; r < 4; r++)
            #pragma unroll
            for (int s = 0; s < 4; s++)
                #pragma unroll
                for (int h = 0; h < 2; h++) {
                    u64t d2v = add2(pj[r][h], nk[s][h]);      // {pj-pk} x2 (FADD2)
                    float lo, hi; unpack2(d2v, lo, hi);
                    // relu fused into FADD.SAT: |d|+cn < 1 so sat == max(0, .)
                    float tl = __saturatef(fabsf(lo) + cnr[r][s]);
                    float th = __saturatef(fabsf(hi) + cnr[r][s]);
                    hs2[s] = add2(hs2[s], pack2(tl, th));     // FADD2 accumulate
                }
    }

    float hsum = 0.0f;
    #pragma unroll
    for (int s = 0; s < 4; s++) {
        float lo, hi; unpack2(hs2[s], lo, hi);
        hsum += lo + hi;
    }

    // ---- reduce + accumulate + epilogue ----
    #pragma unroll
    for (int o = 16; o > 0; o >>= 1) hsum += __shfl_xor_sync(0xffffffffu, hsum, o);
    if (lane == 0) s_red[wid] = hsum;
    __syncthreads();
    if (tid == 0) {
        float bs = 0.0f;
        #pragma unroll
        for (int w = 0; w < NTHR / 32; w++) bs += s_red[w];
        atomicAdd(&g_acc, (double)bs);
        __threadfence();
        int t = atomicAdd(&g_count, 1);
        s_last = (t == NBLK - 1);
    }
    __syncthreads();
    if (s_last && tid == 0) {
        double R  = g_acc;
        double mf = 2.0 * R / ((double)NROWS * (double)(NROWS - 1) * (double)NT);
        out[0] = fmaxf((float)mf - *target, 0.0f);
    }
}

extern "C" void kernel_launch(void* const* d_in, const int* in_sizes, int n_in,
                              void* d_out, int out_size) {
    const float* target = (const float*)d_in[0];
    const float* pred   = (const float*)d_in[1];
    const float* X      = (const float*)d_in[2];
    const float* scale  = (const float*)d_in[4];
    float* out = (float*)d_out;

    cudaFuncSetAttribute(pair_kernel,
                         cudaFuncAttributeMaxDynamicSharedMemorySize, SMEM_BYTES);
    prep_kernel<<<NROWS / 8, 256>>>(X);
    pair_kernel<<<NBLK, NTHR, SMEM_BYTES>>>(pred, scale, target, out);
}